// round 1
// baseline (speedup 1.0000x reference)
#include <cuda_runtime.h>
#include <math.h>

#define BATCH 1024
#define NMAXN 100
#define HD    768
#define AE    128

typedef unsigned long long ull;

// scratch (no allocations allowed)
__device__ float g_sim[BATCH * 256];
__device__ float g_xn[BATCH * 256];

__device__ __forceinline__ ull pack2(float x, float y) {
    ull r; asm("mov.b64 %0, {%1, %2};" : "=l"(r) : "f"(x), "f"(y)); return r;
}
__device__ __forceinline__ float2 unpack2(ull v) {
    float2 r; asm("mov.b64 {%0, %1}, %2;" : "=f"(r.x), "=f"(r.y) : "l"(v)); return r;
}
__device__ __forceinline__ void fma2(ull &acc, ull a, ull b) {
    asm("fma.rn.f32x2 %0, %1, %2, %0;" : "+l"(acc) : "l"(a), "l"(b));
}

// ---------------------------------------------------------------------------
// side_kernel: per (b, side) — fused [node; neigh[0:len]] @ Ww, attention, sim
// grid (1024,2), block 256, dyn smem 84224 B
// ---------------------------------------------------------------------------
__global__ void __launch_bounds__(256, 2) side_kernel(
    const float* __restrict__ node1, const float* __restrict__ node2,
    const float* __restrict__ neigh1, const float* __restrict__ neigh2,
    const float* __restrict__ dist1, const float* __restrict__ dist2,
    const int* __restrict__ len1, const int* __restrict__ len2,
    const float* __restrict__ Ww, const float* __restrict__ bw,
    const float* __restrict__ Wa, const float* __restrict__ ba,
    const float* __restrict__ Wdb, const float* __restrict__ bdb)
{
    extern __shared__ float sm[];
    float* sW   = sm;              // 32*128 = 4096
    float* sA   = sW + 4096;       // 104*32 = 3328
    float* sWng = sA + 3328;       // 101*128 = 12928 (row0 = wn)
    float* sWa  = sWng + 12928;    // 256
    float* sBw  = sWa + 256;       // 128
    float* sDist= sBw + 128;       // 104
    float* sRaw = sDist + 104;     // 104
    float* sAtt = sRaw + 104;      // 104
    float* sC   = sAtt + 104;      // 8
    // total 21056 floats = 84224 bytes

    const int b = blockIdx.x, side = blockIdx.y;
    const float* node  = side ? node2  : node1;
    const float* neigh = side ? neigh2 : neigh1;
    const float* dist  = side ? dist2  : dist1;
    int len = side ? len2[b] : len1[b];
    if (len < 1) len = 1; if (len > NMAXN) len = NMAXN;
    const int M = len + 1;               // row 0 = node, rows 1..len = neighbors

    const int tid = threadIdx.x;
    sWa[tid] = Wa[tid];                   // 256 threads, 256 elems
    if (tid < 128) sBw[tid] = bw[tid];
    if (tid < NMAXN) sDist[tid] = dist[(size_t)b * NMAXN + tid];

    const int lane = tid & 31;            // -> column pairs 2*lane, 2*lane+64
    const int g    = tid >> 5;            // warp id -> rows r = g + 8*i
    ull accA[13], accB[13];
#pragma unroll
    for (int i = 0; i < 13; ++i) { accA[i] = 0ULL; accB[i] = 0ULL; }
    const int nr = (g < M) ? ((M - g + 7) >> 3) : 0;

    const float* nodeRow   = node  + (size_t)b * HD;
    const float* neighBase = neigh + (size_t)b * NMAXN * HD;

    for (int kt = 0; kt < HD / 32; ++kt) {
        const int k0 = kt * 32;
        // W tile: contiguous 4096-float chunk of Ww
#pragma unroll
        for (int p = 0; p < 16; ++p) {
            int e = tid + p * 256;
            sW[e] = Ww[kt * 4096 + e];
        }
        // A tile: rows 0..M-1 (row 0 = node)
        for (int e = tid; e < M * 32; e += 256) {
            int r = e >> 5, kk = e & 31;
            const float* src = (r == 0) ? nodeRow : (neighBase + (size_t)(r - 1) * HD);
            sA[e] = src[k0 + kk];
        }
        __syncthreads();
        for (int kk = 0; kk < 32; ++kk) {
            ull B01 = *(const ull*)(sW + kk * 128 + 2 * lane);
            ull B23 = *(const ull*)(sW + kk * 128 + 2 * lane + 64);
#pragma unroll
            for (int i = 0; i < 13; ++i) {
                if (i < nr) {
                    float a = sA[(g + 8 * i) * 32 + kk];
                    ull A2 = pack2(a, a);
                    fma2(accA[i], A2, B01);
                    fma2(accB[i], A2, B23);
                }
            }
        }
        __syncthreads();
    }

    // epilogue: + bw, write wng (and wn in row 0) to smem
#pragma unroll
    for (int i = 0; i < 13; ++i) {
        if (i < nr) {
            int r = g + 8 * i;
            float2 va = unpack2(accA[i]);
            va.x += sBw[2 * lane];      va.y += sBw[2 * lane + 1];
            *(float2*)(sWng + r * 128 + 2 * lane) = va;
            float2 vb = unpack2(accB[i]);
            vb.x += sBw[2 * lane + 64]; vb.y += sBw[2 * lane + 65];
            *(float2*)(sWng + r * 128 + 2 * lane + 64) = vb;
        }
    }
    __syncthreads();

    // raw attention dots: row 0 -> wn . Wa[0:128], rows>=1 -> wng . Wa[128:256]
    for (int r = g; r < M; r += 8) {
        const float* wrow = sWng + r * 128;
        const float* wa = (r == 0) ? sWa : (sWa + 128);
        float p = 0.f;
#pragma unroll
        for (int q = 0; q < 4; ++q) p += wrow[lane + 32 * q] * wa[lane + 32 * q];
#pragma unroll
        for (int o = 16; o > 0; o >>= 1) p += __shfl_xor_sync(0xffffffffu, p, o);
        if (lane == 0) { if (r == 0) sC[0] = p; else sRaw[r - 1] = p; }
    }
    __syncthreads();

    // warp 0: scores (leaky_relu then dist bias), masked softmax over neighbors
    if (g == 0) {
        float bav = ba[0], wdbv = Wdb[0], bdbv = bdb[0], c = sC[0];
        float sc[4], ev[4];
        float mx = -3.4e38f;
#pragma unroll
        for (int q = 0; q < 4; ++q) {
            int n = lane + 32 * q;
            float v = -3.4e38f;
            if (n < len) {
                float x = c + sRaw[n] + bav;
                x = (x > 0.f) ? x : 0.01f * x;         // leaky_relu(.., 0.01)
                v = x + sDist[n] * wdbv + bdbv;
            }
            sc[q] = v; mx = fmaxf(mx, v);
        }
#pragma unroll
        for (int o = 16; o > 0; o >>= 1) mx = fmaxf(mx, __shfl_xor_sync(0xffffffffu, mx, o));
        float s = 0.f;
#pragma unroll
        for (int q = 0; q < 4; ++q) {
            int n = lane + 32 * q;
            float e = (n < len) ? expf(sc[q] - mx) : 0.f;
            ev[q] = e; s += e;
        }
#pragma unroll
        for (int o = 16; o > 0; o >>= 1) s += __shfl_xor_sync(0xffffffffu, s, o);
        float inv = 1.f / s;
#pragma unroll
        for (int q = 0; q < 4; ++q) {
            int n = lane + 32 * q;
            if (n < NMAXN) sAtt[n] = ev[q] * inv;
        }
    }
    __syncthreads();

    // ctx = sum_n att_n * wng_n ;  sim = ctx * wn
    if (tid < 128) {
        float ctx = 0.f;
        for (int n = 0; n < len; ++n) ctx += sAtt[n] * sWng[(n + 1) * 128 + tid];
        float simv = ctx * sWng[tid];
        g_sim[(size_t)b * 256 + side * 128 + tid] = simv;
    }
}

// ---------------------------------------------------------------------------
// xneigh = relu([sim1,sim2]) @ Wn + bn     grid 128, block 256
// ---------------------------------------------------------------------------
__global__ void xneigh_kernel(const float* __restrict__ Wn, const float* __restrict__ bn)
{
    __shared__ float sS[8 * 256];
    const int b0 = blockIdx.x * 8;
    const int tid = threadIdx.x;
#pragma unroll
    for (int r = 0; r < 8; ++r)
        sS[r * 256 + tid] = fmaxf(g_sim[(size_t)(b0 + r) * 256 + tid], 0.f);
    __syncthreads();
    float acc[8];
    const float bnv = bn[tid];
#pragma unroll
    for (int r = 0; r < 8; ++r) acc[r] = bnv;
#pragma unroll 4
    for (int k = 0; k < 256; ++k) {
        float w = Wn[k * 256 + tid];
#pragma unroll
        for (int r = 0; r < 8; ++r) acc[r] += sS[r * 256 + k] * w;
    }
#pragma unroll
    for (int r = 0; r < 8; ++r) g_xn[(size_t)(b0 + r) * 256 + tid] = acc[r];
}

// ---------------------------------------------------------------------------
// head: h=[pooled,coord,xneigh]; gelu(h@W1+b1); logits=h1@W2+b2; log_softmax
// grid 128 (8 rows/block), block 192, dyn smem 55296 B
// ---------------------------------------------------------------------------
__global__ void head_kernel(
    const float* __restrict__ pooled, const float* __restrict__ x_coord,
    const float* __restrict__ Wc, const float* __restrict__ bc,
    const float* __restrict__ W1, const float* __restrict__ b1,
    const float* __restrict__ W2, const float* __restrict__ b2,
    float* __restrict__ out)
{
    extern __shared__ float sm[];
    float* sH  = sm;             // 8*1152
    float* sH1 = sm + 8 * 1152;  // 8*576
    const int b0 = blockIdx.x * 8;
    const int tid = threadIdx.x;

#pragma unroll
    for (int r = 0; r < 8; ++r) {
        int b = b0 + r;
        for (int j = tid; j < HD; j += 192)  sH[r * 1152 + j] = pooled[(size_t)b * HD + j];
        float xc = x_coord[b];
        for (int j = tid; j < 128; j += 192) sH[r * 1152 + 768 + j] = xc * Wc[j] + bc[j];
        for (int j = tid; j < 256; j += 192) sH[r * 1152 + 896 + j] = g_xn[(size_t)b * 256 + j];
    }
    __syncthreads();

    float acc[8][3];
#pragma unroll
    for (int c = 0; c < 3; ++c) {
        float bv = b1[tid + 192 * c];
#pragma unroll
        for (int r = 0; r < 8; ++r) acc[r][c] = bv;
    }
    float wc_[3], wn_[3];
#pragma unroll
    for (int c = 0; c < 3; ++c) wc_[c] = W1[tid + 192 * c];
    for (int k = 0; k < 1152; ++k) {
        if (k + 1 < 1152) {
#pragma unroll
            for (int c = 0; c < 3; ++c) wn_[c] = W1[(size_t)(k + 1) * 576 + tid + 192 * c];
        }
        float a_[8];
#pragma unroll
        for (int r = 0; r < 8; ++r) a_[r] = sH[r * 1152 + k];
#pragma unroll
        for (int c = 0; c < 3; ++c)
#pragma unroll
            for (int r = 0; r < 8; ++r) acc[r][c] += a_[r] * wc_[c];
#pragma unroll
        for (int c = 0; c < 3; ++c) wc_[c] = wn_[c];
    }

    // exact gelu: x * Phi(x)
#pragma unroll
    for (int c = 0; c < 3; ++c)
#pragma unroll
        for (int r = 0; r < 8; ++r) {
            float x = acc[r][c];
            sH1[r * 576 + tid + 192 * c] = x * normcdff(x);
        }
    __syncthreads();

    const int lane = tid & 31, warp = tid >> 5;
    for (int r = warp; r < 8; r += 6) {
        float p0 = 0.f, p1 = 0.f;
        for (int j = lane; j < 576; j += 32) {
            float h = sH1[r * 576 + j];
            p0 += h * W2[2 * j];
            p1 += h * W2[2 * j + 1];
        }
#pragma unroll
        for (int o = 16; o > 0; o >>= 1) {
            p0 += __shfl_xor_sync(0xffffffffu, p0, o);
            p1 += __shfl_xor_sync(0xffffffffu, p1, o);
        }
        if (lane == 0) {
            float l0 = p0 + b2[0], l1 = p1 + b2[1];
            float m = fmaxf(l0, l1);
            float lse = m + logf(expf(l0 - m) + expf(l1 - m));
            out[(size_t)(b0 + r) * 2 + 0] = l0 - lse;
            out[(size_t)(b0 + r) * 2 + 1] = l1 - lse;
        }
    }
}

// ---------------------------------------------------------------------------
extern "C" void kernel_launch(void* const* d_in, const int* in_sizes, int n_in,
                              void* d_out, int out_size)
{
    const float* pooled = (const float*)d_in[0];
    const float* x_coord= (const float*)d_in[1];
    const float* node1  = (const float*)d_in[2];
    const float* node2  = (const float*)d_in[3];
    const float* neigh1 = (const float*)d_in[4];
    const float* neigh2 = (const float*)d_in[5];
    const float* dist1  = (const float*)d_in[6];
    const float* dist2  = (const float*)d_in[7];
    const int*   len1   = (const int*)d_in[8];
    const int*   len2   = (const int*)d_in[9];
    const float* Ww  = (const float*)d_in[10];
    const float* bw  = (const float*)d_in[11];
    const float* Wa  = (const float*)d_in[12];
    const float* ba  = (const float*)d_in[13];
    const float* Wdb = (const float*)d_in[14];
    const float* bdb = (const float*)d_in[15];
    const float* Wn  = (const float*)d_in[16];
    const float* bn  = (const float*)d_in[17];
    const float* Wc  = (const float*)d_in[18];
    const float* bc  = (const float*)d_in[19];
    const float* W1  = (const float*)d_in[20];
    const float* b1  = (const float*)d_in[21];
    const float* W2  = (const float*)d_in[22];
    const float* b2  = (const float*)d_in[23];
    float* out = (float*)d_out;

    const int smB = 21056 * (int)sizeof(float);   // 84224 B
    cudaFuncSetAttribute(side_kernel, cudaFuncAttributeMaxDynamicSharedMemorySize, smB);
    side_kernel<<<dim3(BATCH, 2), 256, smB>>>(node1, node2, neigh1, neigh2,
                                              dist1, dist2, len1, len2,
                                              Ww, bw, Wa, ba, Wdb, bdb);

    xneigh_kernel<<<BATCH / 8, 256>>>(Wn, bn);

    const int smD = (8 * 1152 + 8 * 576) * (int)sizeof(float);  // 55296 B
    cudaFuncSetAttribute(head_kernel, cudaFuncAttributeMaxDynamicSharedMemorySize, smD);
    head_kernel<<<BATCH / 8, 192, smD>>>(pooled, x_coord, Wc, bc, W1, b1, W2, b2, out);
}

// round 2
// speedup vs baseline: 2.9445x; 2.9445x over previous
#include <cuda_runtime.h>
#include <math.h>
#include <stdint.h>

#define BATCH 1024
#define NMAXN 100
#define HD    768

// ---------------- scratch (no allocations allowed) ----------------
__device__ float g_sim[BATCH * 256];
__device__ float g_xn [BATCH * 256];
// Ww in tf32 fragment layout: [kt(24)][nt(16)][ks(4)][lane(32)][slot(2)]
__device__ float g_Wfrag[24 * 16 * 4 * 32 * 2];

__device__ __forceinline__ uint32_t f2tf(float x) {
    uint32_t t; asm("cvt.rna.tf32.f32 %0, %1;" : "=r"(t) : "f"(x)); return t;
}

__device__ __forceinline__ void mma_tf32(float* c, const uint32_t* a, const uint32_t* b) {
    asm volatile(
        "mma.sync.aligned.m16n8k8.row.col.f32.tf32.tf32.f32 "
        "{%0,%1,%2,%3}, {%4,%5,%6,%7}, {%8,%9}, {%0,%1,%2,%3};"
        : "+f"(c[0]), "+f"(c[1]), "+f"(c[2]), "+f"(c[3])
        : "r"(a[0]), "r"(a[1]), "r"(a[2]), "r"(a[3]), "r"(b[0]), "r"(b[1]));
}

// ---------------------------------------------------------------------------
// wfrag_kernel: Ww [768,128] fp32 -> tf32 fragment layout (run once per launch)
// ---------------------------------------------------------------------------
__global__ void wfrag_kernel(const float* __restrict__ Ww)
{
    int idx = blockIdx.x * 256 + threadIdx.x;      // 0..98303
    int k = idx >> 7, c = idx & 127;
    int kt = k >> 5, kr = k & 31;
    int ks = kr >> 3, k8 = kr & 7, tig = k8 & 3, slot = k8 >> 2;
    int nt = c >> 3, gid = c & 7;
    int lane = gid * 4 + tig;
    g_Wfrag[(((kt * 16 + nt) * 4 + ks) * 32 + lane) * 2 + slot] =
        __uint_as_float(f2tf(Ww[idx]));
}

// ---------------------------------------------------------------------------
// side_kernel: per (b, side) — tf32 tensor-core [node; neigh] @ Ww, attention
// grid (1024,2), block 256 (8 warps), dyn smem 70912 B
// ---------------------------------------------------------------------------
__global__ void __launch_bounds__(256, 2) side_kernel(
    const float* __restrict__ node1, const float* __restrict__ node2,
    const float* __restrict__ neigh1, const float* __restrict__ neigh2,
    const float* __restrict__ dist1, const float* __restrict__ dist2,
    const int* __restrict__ len1, const int* __restrict__ len2,
    const float* __restrict__ bw,
    const float* __restrict__ Wa, const float* __restrict__ ba,
    const float* __restrict__ Wdb, const float* __restrict__ bdb)
{
    extern __shared__ float sm[];
    float* sA   = sm;              // 4096 : A-tile in fragment layout [mt][ks][lane][4]
    float* sWng = sm + 4096;       // 101*128 = 12928 (row0 = wn)
    float* sWa  = sWng + 12928;    // 256
    float* sBw  = sWa + 256;       // 128
    float* sDist= sBw + 128;       // 104
    float* sRaw = sDist + 104;     // 104
    float* sAtt = sRaw + 104;      // 104
    float* sC   = sAtt + 104;      // 8
    // total 17728 floats = 70912 B

    const int b = blockIdx.x, side = blockIdx.y;
    const float* node  = side ? node2  : node1;
    const float* neigh = side ? neigh2 : neigh1;
    const float* dist  = side ? dist2  : dist1;
    int len = side ? len2[b] : len1[b];
    if (len < 1) len = 1; if (len > NMAXN) len = NMAXN;
    const int M = len + 1;                         // row 0 = node
    const int mcount = (M + 15) >> 4;              // 1..7

    const int tid  = threadIdx.x;
    const int warp = tid >> 5, lane = tid & 31;
    const int gid  = lane >> 2, tig = lane & 3;

    sWa[tid] = Wa[tid];
    if (tid < 128) sBw[tid] = bw[tid];
    if (tid < NMAXN) sDist[tid] = dist[(size_t)b * NMAXN + tid];
    // zero A staging (rows >= M keep zeros -> finite garbage-free frags)
#pragma unroll
    for (int i = 0; i < 16; ++i) sA[tid + i * 256] = 0.f;

    const float* nodeRow   = node  + (size_t)b * HD;
    const float* neighBase = neigh + (size_t)b * NMAXN * HD;

    // per-thread staging slots (constant across k-tiles): float4 index f = tid + i*256
    int   nact = 0;                 // how many of the 4 slots are active
    const float* srcp[4];
    int   sbase[4];
#pragma unroll
    for (int i = 0; i < 4; ++i) {
        int f = tid + i * 256;
        if (f < M * 8) {
            int r = f >> 3;
            int mt = r >> 4, r16 = r & 15, g8 = r16 & 7, hi = r16 >> 3;
            int ksl = (f & 7) >> 1, kh = f & 1;
            srcp[i]  = (r == 0 ? nodeRow : neighBase + (size_t)(r - 1) * HD) + (f & 7) * 4;
            sbase[i] = (mt * 4 + ksl) * 128 + (g8 * 4) * 4 + (kh * 2 + hi);
            nact = i + 1;
        }
    }

    float acc[7][2][4];
#pragma unroll
    for (int mt = 0; mt < 7; ++mt)
#pragma unroll
        for (int ni = 0; ni < 2; ++ni)
#pragma unroll
            for (int q = 0; q < 4; ++q) acc[mt][ni][q] = 0.f;

    float4 v[4];
#pragma unroll
    for (int i = 0; i < 4; ++i) if (i < nact) v[i] = *(const float4*)(srcp[i]);

    __syncthreads();   // zero-fill + staging tables done

    for (int kt = 0; kt < 24; ++kt) {
        // commit prefetched tile (fp32 -> tf32, fragment-ordered STS)
#pragma unroll
        for (int i = 0; i < 4; ++i) {
            if (i < nact) {
                sA[sbase[i] + 0 ] = __uint_as_float(f2tf(v[i].x));
                sA[sbase[i] + 4 ] = __uint_as_float(f2tf(v[i].y));
                sA[sbase[i] + 8 ] = __uint_as_float(f2tf(v[i].z));
                sA[sbase[i] + 12] = __uint_as_float(f2tf(v[i].w));
            }
        }
        // prefetch next tile
        if (kt < 23) {
#pragma unroll
            for (int i = 0; i < 4; ++i)
                if (i < nact) v[i] = *(const float4*)(srcp[i] + (kt + 1) * 32);
        }
        __syncthreads();

        // B fragments for this k-tile (hot in L1/L2, shared by all blocks)
        uint32_t bfr[2][4][2];
#pragma unroll
        for (int ni = 0; ni < 2; ++ni) {
            int nt = 2 * warp + ni;
#pragma unroll
            for (int ks = 0; ks < 4; ++ks) {
                float2 bv = *(const float2*)(g_Wfrag +
                    (((kt * 16 + nt) * 4 + ks) * 32 + lane) * 2);
                bfr[ni][ks][0] = __float_as_uint(bv.x);
                bfr[ni][ks][1] = __float_as_uint(bv.y);
            }
        }
#pragma unroll
        for (int ks = 0; ks < 4; ++ks) {
#pragma unroll
            for (int mt = 0; mt < 7; ++mt) {
                if (mt >= mcount) break;            // uniform: no dead HMMA issue
                float4 av = *(const float4*)(sA + (mt * 4 + ks) * 128 + lane * 4);
                uint32_t a[4] = { __float_as_uint(av.x), __float_as_uint(av.y),
                                  __float_as_uint(av.z), __float_as_uint(av.w) };
                mma_tf32(acc[mt][0], a, bfr[0][ks]);
                mma_tf32(acc[mt][1], a, bfr[1][ks]);
            }
        }
        __syncthreads();
    }

    // epilogue: + bw, scatter accumulators into sWng
#pragma unroll
    for (int mt = 0; mt < 7; ++mt) {
        if (mt >= mcount) break;
        int r0 = mt * 16 + gid, r1 = r0 + 8;
#pragma unroll
        for (int ni = 0; ni < 2; ++ni) {
            int cc = (2 * warp + ni) * 8 + tig * 2;
            if (r0 < M) {
                float2 o = { acc[mt][ni][0] + sBw[cc], acc[mt][ni][1] + sBw[cc + 1] };
                *(float2*)(sWng + r0 * 128 + cc) = o;
            }
            if (r1 < M) {
                float2 o = { acc[mt][ni][2] + sBw[cc], acc[mt][ni][3] + sBw[cc + 1] };
                *(float2*)(sWng + r1 * 128 + cc) = o;
            }
        }
    }
    __syncthreads();

    // raw attention dots: row 0 -> wn . Wa[0:128], rows>=1 -> wng . Wa[128:256]
    for (int r = warp; r < M; r += 8) {
        const float* wrow = sWng + r * 128;
        const float* wa = (r == 0) ? sWa : (sWa + 128);
        float p = 0.f;
#pragma unroll
        for (int q = 0; q < 4; ++q) p += wrow[lane + 32 * q] * wa[lane + 32 * q];
#pragma unroll
        for (int o = 16; o > 0; o >>= 1) p += __shfl_xor_sync(0xffffffffu, p, o);
        if (lane == 0) { if (r == 0) sC[0] = p; else sRaw[r - 1] = p; }
    }
    __syncthreads();

    // warp 0: leaky_relu + dist bias, masked softmax over neighbors
    if (warp == 0) {
        float bav = ba[0], wdbv = Wdb[0], bdbv = bdb[0], c = sC[0];
        float sc[4], ev[4];
        float mx = -3.4e38f;
#pragma unroll
        for (int q = 0; q < 4; ++q) {
            int n = lane + 32 * q;
            float vv = -3.4e38f;
            if (n < len) {
                float x = c + sRaw[n] + bav;
                x = (x > 0.f) ? x : 0.01f * x;
                vv = x + sDist[n] * wdbv + bdbv;
            }
            sc[q] = vv; mx = fmaxf(mx, vv);
        }
#pragma unroll
        for (int o = 16; o > 0; o >>= 1) mx = fmaxf(mx, __shfl_xor_sync(0xffffffffu, mx, o));
        float s = 0.f;
#pragma unroll
        for (int q = 0; q < 4; ++q) {
            int n = lane + 32 * q;
            float e = (n < len) ? expf(sc[q] - mx) : 0.f;
            ev[q] = e; s += e;
        }
#pragma unroll
        for (int o = 16; o > 0; o >>= 1) s += __shfl_xor_sync(0xffffffffu, s, o);
        float inv = 1.f / s;
#pragma unroll
        for (int q = 0; q < 4; ++q) {
            int n = lane + 32 * q;
            if (n < NMAXN) sAtt[n] = ev[q] * inv;
        }
    }
    __syncthreads();

    // ctx = sum_n att_n * wng_n ;  sim = ctx * wn
    if (tid < 128) {
        float ctx = 0.f;
        for (int n = 0; n < len; ++n) ctx += sAtt[n] * sWng[(n + 1) * 128 + tid];
        g_sim[(size_t)b * 256 + side * 128 + tid] = ctx * sWng[tid];
    }
}

// ---------------------------------------------------------------------------
// xneigh = relu([sim1,sim2]) @ Wn + bn     grid 128, block 256
// ---------------------------------------------------------------------------
__global__ void xneigh_kernel(const float* __restrict__ Wn, const float* __restrict__ bn)
{
    __shared__ float sS[8 * 256];
    const int b0 = blockIdx.x * 8;
    const int tid = threadIdx.x;
#pragma unroll
    for (int r = 0; r < 8; ++r)
        sS[r * 256 + tid] = fmaxf(g_sim[(size_t)(b0 + r) * 256 + tid], 0.f);
    __syncthreads();
    float acc[8];
    const float bnv = bn[tid];
#pragma unroll
    for (int r = 0; r < 8; ++r) acc[r] = bnv;
#pragma unroll 4
    for (int k = 0; k < 256; ++k) {
        float w = Wn[k * 256 + tid];
#pragma unroll
        for (int r = 0; r < 8; ++r) acc[r] += sS[r * 256 + k] * w;
    }
#pragma unroll
    for (int r = 0; r < 8; ++r) g_xn[(size_t)(b0 + r) * 256 + tid] = acc[r];
}

// ---------------------------------------------------------------------------
// head: h=[pooled,coord,xneigh]; gelu(h@W1+b1); logits=h1@W2+b2; log_softmax
// grid 128 (8 rows/block), block 192, dyn smem 55296 B
// ---------------------------------------------------------------------------
__global__ void head_kernel(
    const float* __restrict__ pooled, const float* __restrict__ x_coord,
    const float* __restrict__ Wc, const float* __restrict__ bc,
    const float* __restrict__ W1, const float* __restrict__ b1,
    const float* __restrict__ W2, const float* __restrict__ b2,
    float* __restrict__ out)
{
    extern __shared__ float sm[];
    float* sH  = sm;             // 8*1152
    float* sH1 = sm + 8 * 1152;  // 8*576
    const int b0 = blockIdx.x * 8;
    const int tid = threadIdx.x;

#pragma unroll
    for (int r = 0; r < 8; ++r) {
        int b = b0 + r;
        for (int j = tid; j < HD; j += 192)  sH[r * 1152 + j] = pooled[(size_t)b * HD + j];
        float xc = x_coord[b];
        for (int j = tid; j < 128; j += 192) sH[r * 1152 + 768 + j] = xc * Wc[j] + bc[j];
        for (int j = tid; j < 256; j += 192) sH[r * 1152 + 896 + j] = g_xn[(size_t)b * 256 + j];
    }
    __syncthreads();

    float acc[8][3];
#pragma unroll
    for (int c = 0; c < 3; ++c) {
        float bv = b1[tid + 192 * c];
#pragma unroll
        for (int r = 0; r < 8; ++r) acc[r][c] = bv;
    }
    float wc_[3], wn_[3];
#pragma unroll
    for (int c = 0; c < 3; ++c) wc_[c] = W1[tid + 192 * c];
    for (int k = 0; k < 1152; ++k) {
        if (k + 1 < 1152) {
#pragma unroll
            for (int c = 0; c < 3; ++c) wn_[c] = W1[(size_t)(k + 1) * 576 + tid + 192 * c];
        }
        float a_[8];
#pragma unroll
        for (int r = 0; r < 8; ++r) a_[r] = sH[r * 1152 + k];
#pragma unroll
        for (int c = 0; c < 3; ++c)
#pragma unroll
            for (int r = 0; r < 8; ++r) acc[r][c] += a_[r] * wc_[c];
#pragma unroll
        for (int c = 0; c < 3; ++c) wc_[c] = wn_[c];
    }

#pragma unroll
    for (int c = 0; c < 3; ++c)
#pragma unroll
        for (int r = 0; r < 8; ++r) {
            float x = acc[r][c];
            sH1[r * 576 + tid + 192 * c] = x * normcdff(x);
        }
    __syncthreads();

    const int lane = tid & 31, warp = tid >> 5;
    for (int r = warp; r < 8; r += 6) {
        float p0 = 0.f, p1 = 0.f;
        for (int j = lane; j < 576; j += 32) {
            float h = sH1[r * 576 + j];
            p0 += h * W2[2 * j];
            p1 += h * W2[2 * j + 1];
        }
#pragma unroll
        for (int o = 16; o > 0; o >>= 1) {
            p0 += __shfl_xor_sync(0xffffffffu, p0, o);
            p1 += __shfl_xor_sync(0xffffffffu, p1, o);
        }
        if (lane == 0) {
            float l0 = p0 + b2[0], l1 = p1 + b2[1];
            float m = fmaxf(l0, l1);
            float lse = m + logf(expf(l0 - m) + expf(l1 - m));
            out[(size_t)(b0 + r) * 2 + 0] = l0 - lse;
            out[(size_t)(b0 + r) * 2 + 1] = l1 - lse;
        }
    }
}

// ---------------------------------------------------------------------------
extern "C" void kernel_launch(void* const* d_in, const int* in_sizes, int n_in,
                              void* d_out, int out_size)
{
    const float* pooled = (const float*)d_in[0];
    const float* x_coord= (const float*)d_in[1];
    const float* node1  = (const float*)d_in[2];
    const float* node2  = (const float*)d_in[3];
    const float* neigh1 = (const float*)d_in[4];
    const float* neigh2 = (const float*)d_in[5];
    const float* dist1  = (const float*)d_in[6];
    const float* dist2  = (const float*)d_in[7];
    const int*   len1   = (const int*)d_in[8];
    const int*   len2   = (const int*)d_in[9];
    const float* Ww  = (const float*)d_in[10];
    const float* bw  = (const float*)d_in[11];
    const float* Wa  = (const float*)d_in[12];
    const float* ba  = (const float*)d_in[13];
    const float* Wdb = (const float*)d_in[14];
    const float* bdb = (const float*)d_in[15];
    const float* Wn  = (const float*)d_in[16];
    const float* bn  = (const float*)d_in[17];
    const float* Wc  = (const float*)d_in[18];
    const float* bc  = (const float*)d_in[19];
    const float* W1  = (const float*)d_in[20];
    const float* b1  = (const float*)d_in[21];
    const float* W2  = (const float*)d_in[22];
    const float* b2  = (const float*)d_in[23];
    float* out = (float*)d_out;

    wfrag_kernel<<<384, 256>>>(Ww);

    const int smB = 17728 * (int)sizeof(float);   // 70912 B
    cudaFuncSetAttribute(side_kernel, cudaFuncAttributeMaxDynamicSharedMemorySize, smB);
    side_kernel<<<dim3(BATCH, 2), 256, smB>>>(node1, node2, neigh1, neigh2,
                                              dist1, dist2, len1, len2,
                                              bw, Wa, ba, Wdb, bdb);

    xneigh_kernel<<<BATCH / 8, 256>>>(Wn, bn);

    const int smD = (8 * 1152 + 8 * 576) * (int)sizeof(float);  // 55296 B
    cudaFuncSetAttribute(head_kernel, cudaFuncAttributeMaxDynamicSharedMemorySize, smD);
    head_kernel<<<BATCH / 8, 192, smD>>>(pooled, x_coord, Wc, bc, W1, b1, W2, b2, out);
}

// round 3
// speedup vs baseline: 4.7736x; 1.6212x over previous
#include <cuda_runtime.h>
#include <math.h>
#include <stdint.h>

#define BATCH 1024
#define NMAXN 100
#define HD    768

// ---------------- scratch (no allocations allowed) ----------------
__device__ float g_sim[BATCH * 256];
__device__ float g_xn [BATCH * 256];
__device__ float g_h  [BATCH * 1152];
__device__ float g_h1 [BATCH * 576];
// Ww in tf32 fragment layout: [kt(24)][nt(16)][ks(4)][lane(32)][slot(2)]
__device__ float g_Wfrag[24 * 16 * 4 * 32 * 2];
// W1 in tf32 fragment layout: [kt(36)][nt(72)][ks(4)][lane(32)][slot(2)]
__device__ float g_W1frag[36 * 72 * 4 * 32 * 2];

__device__ __forceinline__ uint32_t f2tf(float x) {
    uint32_t t; asm("cvt.rna.tf32.f32 %0, %1;" : "=r"(t) : "f"(x)); return t;
}

__device__ __forceinline__ void mma_tf32(float* c, const uint32_t* a, const uint32_t* b) {
    asm volatile(
        "mma.sync.aligned.m16n8k8.row.col.f32.tf32.tf32.f32 "
        "{%0,%1,%2,%3}, {%4,%5,%6,%7}, {%8,%9}, {%0,%1,%2,%3};"
        : "+f"(c[0]), "+f"(c[1]), "+f"(c[2]), "+f"(c[3])
        : "r"(a[0]), "r"(a[1]), "r"(a[2]), "r"(a[3]), "r"(b[0]), "r"(b[1]));
}

// ---------------------------------------------------------------------------
// wfrag_kernel: Ww [768,128] fp32 -> tf32 fragment layout
// ---------------------------------------------------------------------------
__global__ void wfrag_kernel(const float* __restrict__ Ww)
{
    int idx = blockIdx.x * 256 + threadIdx.x;      // 0..98303
    int k = idx >> 7, c = idx & 127;
    int kt = k >> 5, kr = k & 31;
    int ks = kr >> 3, k8 = kr & 7, tig = k8 & 3, slot = k8 >> 2;
    int nt = c >> 3, gid = c & 7;
    int lane = gid * 4 + tig;
    g_Wfrag[(((kt * 16 + nt) * 4 + ks) * 32 + lane) * 2 + slot] =
        __uint_as_float(f2tf(Ww[idx]));
}

// ---------------------------------------------------------------------------
// w1frag_kernel: W1 [1152,576] fp32 -> tf32 fragment layout
// ---------------------------------------------------------------------------
__global__ void w1frag_kernel(const float* __restrict__ W1)
{
    int idx = blockIdx.x * 256 + threadIdx.x;      // 0..663551
    int k = idx / 576, c = idx - k * 576;
    int kt = k >> 5, kr = k & 31;
    int ks = kr >> 3, k8 = kr & 7, tig = k8 & 3, slot = k8 >> 2;
    int nt = c >> 3, gid = c & 7;
    int lane = gid * 4 + tig;
    g_W1frag[(((kt * 72 + nt) * 4 + ks) * 32 + lane) * 2 + slot] =
        __uint_as_float(f2tf(W1[idx]));
}

// ---------------------------------------------------------------------------
// side_kernel: per (b, side) — tf32 tensor-core [node; neigh] @ Ww, attention
// ---------------------------------------------------------------------------
__global__ void __launch_bounds__(256, 2) side_kernel(
    const float* __restrict__ node1, const float* __restrict__ node2,
    const float* __restrict__ neigh1, const float* __restrict__ neigh2,
    const float* __restrict__ dist1, const float* __restrict__ dist2,
    const int* __restrict__ len1, const int* __restrict__ len2,
    const float* __restrict__ bw,
    const float* __restrict__ Wa, const float* __restrict__ ba,
    const float* __restrict__ Wdb, const float* __restrict__ bdb)
{
    extern __shared__ float sm[];
    float* sA   = sm;              // 4096
    float* sWng = sm + 4096;       // 12928
    float* sWa  = sWng + 12928;    // 256
    float* sBw  = sWa + 256;       // 128
    float* sDist= sBw + 128;       // 104
    float* sRaw = sDist + 104;     // 104
    float* sAtt = sRaw + 104;      // 104
    float* sC   = sAtt + 104;      // 8

    const int b = blockIdx.x, side = blockIdx.y;
    const float* node  = side ? node2  : node1;
    const float* neigh = side ? neigh2 : neigh1;
    const float* dist  = side ? dist2  : dist1;
    int len = side ? len2[b] : len1[b];
    if (len < 1) len = 1; if (len > NMAXN) len = NMAXN;
    const int M = len + 1;
    const int mcount = (M + 15) >> 4;

    const int tid  = threadIdx.x;
    const int warp = tid >> 5, lane = tid & 31;
    const int gid  = lane >> 2, tig = lane & 3;

    sWa[tid] = Wa[tid];
    if (tid < 128) sBw[tid] = bw[tid];
    if (tid < NMAXN) sDist[tid] = dist[(size_t)b * NMAXN + tid];
#pragma unroll
    for (int i = 0; i < 16; ++i) sA[tid + i * 256] = 0.f;

    const float* nodeRow   = node  + (size_t)b * HD;
    const float* neighBase = neigh + (size_t)b * NMAXN * HD;

    int   nact = 0;
    const float* srcp[4];
    int   sbase[4];
#pragma unroll
    for (int i = 0; i < 4; ++i) {
        int f = tid + i * 256;
        if (f < M * 8) {
            int r = f >> 3;
            int mt = r >> 4, r16 = r & 15, g8 = r16 & 7, hi = r16 >> 3;
            int ksl = (f & 7) >> 1, kh = f & 1;
            srcp[i]  = (r == 0 ? nodeRow : neighBase + (size_t)(r - 1) * HD) + (f & 7) * 4;
            sbase[i] = (mt * 4 + ksl) * 128 + (g8 * 4) * 4 + (kh * 2 + hi);
            nact = i + 1;
        }
    }

    float acc[7][2][4];
#pragma unroll
    for (int mt = 0; mt < 7; ++mt)
#pragma unroll
        for (int ni = 0; ni < 2; ++ni)
#pragma unroll
            for (int q = 0; q < 4; ++q) acc[mt][ni][q] = 0.f;

    float4 v[4];
#pragma unroll
    for (int i = 0; i < 4; ++i) if (i < nact) v[i] = *(const float4*)(srcp[i]);

    __syncthreads();

    for (int kt = 0; kt < 24; ++kt) {
#pragma unroll
        for (int i = 0; i < 4; ++i) {
            if (i < nact) {
                sA[sbase[i] + 0 ] = __uint_as_float(f2tf(v[i].x));
                sA[sbase[i] + 4 ] = __uint_as_float(f2tf(v[i].y));
                sA[sbase[i] + 8 ] = __uint_as_float(f2tf(v[i].z));
                sA[sbase[i] + 12] = __uint_as_float(f2tf(v[i].w));
            }
        }
        if (kt < 23) {
#pragma unroll
            for (int i = 0; i < 4; ++i)
                if (i < nact) v[i] = *(const float4*)(srcp[i] + (kt + 1) * 32);
        }
        __syncthreads();

        uint32_t bfr[2][4][2];
#pragma unroll
        for (int ni = 0; ni < 2; ++ni) {
            int nt = 2 * warp + ni;
#pragma unroll
            for (int ks = 0; ks < 4; ++ks) {
                float2 bv = *(const float2*)(g_Wfrag +
                    (((kt * 16 + nt) * 4 + ks) * 32 + lane) * 2);
                bfr[ni][ks][0] = __float_as_uint(bv.x);
                bfr[ni][ks][1] = __float_as_uint(bv.y);
            }
        }
#pragma unroll
        for (int ks = 0; ks < 4; ++ks) {
#pragma unroll
            for (int mt = 0; mt < 7; ++mt) {
                if (mt >= mcount) break;
                float4 av = *(const float4*)(sA + (mt * 4 + ks) * 128 + lane * 4);
                uint32_t a[4] = { __float_as_uint(av.x), __float_as_uint(av.y),
                                  __float_as_uint(av.z), __float_as_uint(av.w) };
                mma_tf32(acc[mt][0], a, bfr[0][ks]);
                mma_tf32(acc[mt][1], a, bfr[1][ks]);
            }
        }
        __syncthreads();
    }

#pragma unroll
    for (int mt = 0; mt < 7; ++mt) {
        if (mt >= mcount) break;
        int r0 = mt * 16 + gid, r1 = r0 + 8;
#pragma unroll
        for (int ni = 0; ni < 2; ++ni) {
            int cc = (2 * warp + ni) * 8 + tig * 2;
            if (r0 < M) {
                float2 o = { acc[mt][ni][0] + sBw[cc], acc[mt][ni][1] + sBw[cc + 1] };
                *(float2*)(sWng + r0 * 128 + cc) = o;
            }
            if (r1 < M) {
                float2 o = { acc[mt][ni][2] + sBw[cc], acc[mt][ni][3] + sBw[cc + 1] };
                *(float2*)(sWng + r1 * 128 + cc) = o;
            }
        }
    }
    __syncthreads();

    for (int r = warp; r < M; r += 8) {
        const float* wrow = sWng + r * 128;
        const float* wa = (r == 0) ? sWa : (sWa + 128);
        float p = 0.f;
#pragma unroll
        for (int q = 0; q < 4; ++q) p += wrow[lane + 32 * q] * wa[lane + 32 * q];
#pragma unroll
        for (int o = 16; o > 0; o >>= 1) p += __shfl_xor_sync(0xffffffffu, p, o);
        if (lane == 0) { if (r == 0) sC[0] = p; else sRaw[r - 1] = p; }
    }
    __syncthreads();

    if (warp == 0) {
        float bav = ba[0], wdbv = Wdb[0], bdbv = bdb[0], c = sC[0];
        float sc[4], ev[4];
        float mx = -3.4e38f;
#pragma unroll
        for (int q = 0; q < 4; ++q) {
            int n = lane + 32 * q;
            float vv = -3.4e38f;
            if (n < len) {
                float x = c + sRaw[n] + bav;
                x = (x > 0.f) ? x : 0.01f * x;
                vv = x + sDist[n] * wdbv + bdbv;
            }
            sc[q] = vv; mx = fmaxf(mx, vv);
        }
#pragma unroll
        for (int o = 16; o > 0; o >>= 1) mx = fmaxf(mx, __shfl_xor_sync(0xffffffffu, mx, o));
        float s = 0.f;
#pragma unroll
        for (int q = 0; q < 4; ++q) {
            int n = lane + 32 * q;
            float e = (n < len) ? expf(sc[q] - mx) : 0.f;
            ev[q] = e; s += e;
        }
#pragma unroll
        for (int o = 16; o > 0; o >>= 1) s += __shfl_xor_sync(0xffffffffu, s, o);
        float inv = 1.f / s;
#pragma unroll
        for (int q = 0; q < 4; ++q) {
            int n = lane + 32 * q;
            if (n < NMAXN) sAtt[n] = ev[q] * inv;
        }
    }
    __syncthreads();

    if (tid < 128) {
        float ctx = 0.f;
        for (int n = 0; n < len; ++n) ctx += sAtt[n] * sWng[(n + 1) * 128 + tid];
        g_sim[(size_t)b * 256 + side * 128 + tid] = ctx * sWng[tid];
    }
}

// ---------------------------------------------------------------------------
// xneigh = relu([sim1,sim2]) @ Wn + bn     grid 128, block 256
// ---------------------------------------------------------------------------
__global__ void xneigh_kernel(const float* __restrict__ Wn, const float* __restrict__ bn)
{
    __shared__ float sS[8 * 256];
    const int b0 = blockIdx.x * 8;
    const int tid = threadIdx.x;
#pragma unroll
    for (int r = 0; r < 8; ++r)
        sS[r * 256 + tid] = fmaxf(g_sim[(size_t)(b0 + r) * 256 + tid], 0.f);
    __syncthreads();
    float acc[8];
    const float bnv = bn[tid];
#pragma unroll
    for (int r = 0; r < 8; ++r) acc[r] = bnv;
#pragma unroll 4
    for (int k = 0; k < 256; ++k) {
        float w = Wn[k * 256 + tid];
#pragma unroll
        for (int r = 0; r < 8; ++r) acc[r] += sS[r * 256 + k] * w;
    }
#pragma unroll
    for (int r = 0; r < 8; ++r) g_xn[(size_t)(b0 + r) * 256 + tid] = acc[r];
}

// ---------------------------------------------------------------------------
// build_h: g_h[b][0:768]=pooled, [768:896]=coord, [896:1152]=xneigh
// ---------------------------------------------------------------------------
__global__ void build_h_kernel(
    const float* __restrict__ pooled, const float* __restrict__ x_coord,
    const float* __restrict__ Wc, const float* __restrict__ bc)
{
    int idx = blockIdx.x * 256 + threadIdx.x;      // 0 .. 1024*1152-1
    int b = idx / 1152, j = idx - b * 1152;
    float v;
    if (j < 768)       v = pooled[(size_t)b * 768 + j];
    else if (j < 896)  v = x_coord[b] * Wc[j - 768] + bc[j - 768];
    else               v = g_xn[(size_t)b * 256 + (j - 896)];
    g_h[idx] = v;
}

// ---------------------------------------------------------------------------
// head_mm: g_h1 = gelu(g_h @ W1 + b1)   tf32 tensor cores
// grid (16,9) = 64x64 tiles, block 256 (8 warps), smem 8KB
// ---------------------------------------------------------------------------
__global__ void __launch_bounds__(256, 2) head_mm_kernel(const float* __restrict__ b1)
{
    __shared__ float sA[2048];     // [mt(4)][ks(4)][lane(32)][4]

    const int tid  = threadIdx.x;
    const int warp = tid >> 5, lane = tid & 31;
    const int gid  = lane >> 2, tig = lane & 3;
    const int m0   = blockIdx.x * 64;
    const int ntg  = blockIdx.y * 8 + warp;        // global n-tile (8 cols)

    // staging slots: f = tid + i*256, i=0..1 (512 float4 = 64 rows x 32 k)
    const float* srcp[2];
    int sbase[2];
#pragma unroll
    for (int i = 0; i < 2; ++i) {
        int f = tid + i * 256;
        int r = f >> 3;
        int mt = r >> 4, r16 = r & 15, g8 = r16 & 7, hi = r16 >> 3;
        int ksl = (f & 7) >> 1, kh = f & 1;
        srcp[i]  = g_h + (size_t)(m0 + r) * 1152 + (f & 7) * 4;
        sbase[i] = (mt * 4 + ksl) * 128 + (g8 * 4) * 4 + (kh * 2 + hi);
    }

    float acc[4][4];
#pragma unroll
    for (int mt = 0; mt < 4; ++mt)
#pragma unroll
        for (int q = 0; q < 4; ++q) acc[mt][q] = 0.f;

    float4 v[2];
#pragma unroll
    for (int i = 0; i < 2; ++i) v[i] = *(const float4*)(srcp[i]);

    for (int kt = 0; kt < 36; ++kt) {
#pragma unroll
        for (int i = 0; i < 2; ++i) {
            sA[sbase[i] + 0 ] = __uint_as_float(f2tf(v[i].x));
            sA[sbase[i] + 4 ] = __uint_as_float(f2tf(v[i].y));
            sA[sbase[i] + 8 ] = __uint_as_float(f2tf(v[i].z));
            sA[sbase[i] + 12] = __uint_as_float(f2tf(v[i].w));
        }
        if (kt < 35) {
#pragma unroll
            for (int i = 0; i < 2; ++i) v[i] = *(const float4*)(srcp[i] + (kt + 1) * 32);
        }
        __syncthreads();

        uint32_t bfr[4][2];
#pragma unroll
        for (int ks = 0; ks < 4; ++ks) {
            float2 bv = *(const float2*)(g_W1frag +
                (((kt * 72 + ntg) * 4 + ks) * 32 + lane) * 2);
            bfr[ks][0] = __float_as_uint(bv.x);
            bfr[ks][1] = __float_as_uint(bv.y);
        }
#pragma unroll
        for (int ks = 0; ks < 4; ++ks) {
#pragma unroll
            for (int mt = 0; mt < 4; ++mt) {
                float4 av = *(const float4*)(sA + (mt * 4 + ks) * 128 + lane * 4);
                uint32_t a[4] = { __float_as_uint(av.x), __float_as_uint(av.y),
                                  __float_as_uint(av.z), __float_as_uint(av.w) };
                mma_tf32(acc[mt], a, bfr[ks]);
            }
        }
        __syncthreads();
    }

    // epilogue: + b1, exact gelu, write g_h1
    const int cc = ntg * 8 + tig * 2;
    const float bv0 = b1[cc], bv1 = b1[cc + 1];
#pragma unroll
    for (int mt = 0; mt < 4; ++mt) {
        int r0 = m0 + mt * 16 + gid, r1 = r0 + 8;
        float x;
        x = acc[mt][0] + bv0; g_h1[(size_t)r0 * 576 + cc]     = x * normcdff(x);
        x = acc[mt][1] + bv1; g_h1[(size_t)r0 * 576 + cc + 1] = x * normcdff(x);
        x = acc[mt][2] + bv0; g_h1[(size_t)r1 * 576 + cc]     = x * normcdff(x);
        x = acc[mt][3] + bv1; g_h1[(size_t)r1 * 576 + cc + 1] = x * normcdff(x);
    }
}

// ---------------------------------------------------------------------------
// logits: out = log_softmax(g_h1 @ W2 + b2)   grid 128, block 256 (8 warps)
// ---------------------------------------------------------------------------
__global__ void logits_kernel(const float* __restrict__ W2, const float* __restrict__ b2,
                              float* __restrict__ out)
{
    __shared__ float sW2[1152];
    const int tid = threadIdx.x;
    const int lane = tid & 31, warp = tid >> 5;
    for (int j = tid; j < 1152; j += 256) sW2[j] = W2[j];
    __syncthreads();

    const int r = blockIdx.x * 8 + warp;
    float p0 = 0.f, p1 = 0.f;
    const float* hrow = g_h1 + (size_t)r * 576;
#pragma unroll
    for (int q = 0; q < 18; ++q) {
        int j = lane + 32 * q;
        float h = hrow[j];
        p0 += h * sW2[2 * j];
        p1 += h * sW2[2 * j + 1];
    }
#pragma unroll
    for (int o = 16; o > 0; o >>= 1) {
        p0 += __shfl_xor_sync(0xffffffffu, p0, o);
        p1 += __shfl_xor_sync(0xffffffffu, p1, o);
    }
    if (lane == 0) {
        float l0 = p0 + b2[0], l1 = p1 + b2[1];
        float m = fmaxf(l0, l1);
        float lse = m + logf(expf(l0 - m) + expf(l1 - m));
        out[(size_t)r * 2 + 0] = l0 - lse;
        out[(size_t)r * 2 + 1] = l1 - lse;
    }
}

// ---------------------------------------------------------------------------
extern "C" void kernel_launch(void* const* d_in, const int* in_sizes, int n_in,
                              void* d_out, int out_size)
{
    const float* pooled = (const float*)d_in[0];
    const float* x_coord= (const float*)d_in[1];
    const float* node1  = (const float*)d_in[2];
    const float* node2  = (const float*)d_in[3];
    const float* neigh1 = (const float*)d_in[4];
    const float* neigh2 = (const float*)d_in[5];
    const float* dist1  = (const float*)d_in[6];
    const float* dist2  = (const float*)d_in[7];
    const int*   len1   = (const int*)d_in[8];
    const int*   len2   = (const int*)d_in[9];
    const float* Ww  = (const float*)d_in[10];
    const float* bw  = (const float*)d_in[11];
    const float* Wa  = (const float*)d_in[12];
    const float* ba  = (const float*)d_in[13];
    const float* Wdb = (const float*)d_in[14];
    const float* bdb = (const float*)d_in[15];
    const float* Wn  = (const float*)d_in[16];
    const float* bn  = (const float*)d_in[17];
    const float* Wc  = (const float*)d_in[18];
    const float* bc  = (const float*)d_in[19];
    const float* W1  = (const float*)d_in[20];
    const float* b1  = (const float*)d_in[21];
    const float* W2  = (const float*)d_in[22];
    const float* b2  = (const float*)d_in[23];
    float* out = (float*)d_out;

    wfrag_kernel<<<384, 256>>>(Ww);
    w1frag_kernel<<<2592, 256>>>(W1);

    const int smB = 17728 * (int)sizeof(float);   // 70912 B
    cudaFuncSetAttribute(side_kernel, cudaFuncAttributeMaxDynamicSharedMemorySize, smB);
    side_kernel<<<dim3(BATCH, 2), 256, smB>>>(node1, node2, neigh1, neigh2,
                                              dist1, dist2, len1, len2,
                                              bw, Wa, ba, Wdb, bdb);

    xneigh_kernel<<<BATCH / 8, 256>>>(Wn, bn);

    build_h_kernel<<<(BATCH * 1152) / 256, 256>>>(pooled, x_coord, Wc, bc);

    head_mm_kernel<<<dim3(16, 9), 256>>>(b1);

    logits_kernel<<<BATCH / 8, 256>>>(W2, b2, out);
}

// round 4
// speedup vs baseline: 6.4548x; 1.3522x over previous
#include <cuda_runtime.h>
#include <cuda_bf16.h>
#include <math.h>
#include <stdint.h>

#define BATCH 1024
#define NMAXN 100
#define HD    768

// ---------------- scratch (no allocations allowed) ----------------
__device__ float g_sim[BATCH * 256];
__device__ float g_xn [BATCH * 256];
__device__ float g_h  [BATCH * 1152];
__device__ float g_h1 [BATCH * 576];
__device__ unsigned g_counter;
// Ww in bf16 fragment layout for m16n8k16: [kt(24)][nt(16)][lane(32)][reg(4)] (uint32 = bf16x2)
__device__ __align__(16) uint32_t g_WfragB[24 * 16 * 32 * 4];
// W1 in tf32 fragment layout: [kt(36)][nt(72)][ks(4)][lane(32)][slot(2)]
__device__ float g_W1frag[36 * 72 * 4 * 32 * 2];

__device__ __forceinline__ uint32_t f2tf(float x) {
    uint32_t t; asm("cvt.rna.tf32.f32 %0, %1;" : "=r"(t) : "f"(x)); return t;
}
__device__ __forceinline__ uint32_t pack_bf2(float lo, float hi) {
    __nv_bfloat162 p = __float22bfloat162_rn(make_float2(lo, hi));
    return *(uint32_t*)&p;
}

__device__ __forceinline__ void mma_tf32(float* c, const uint32_t* a, const uint32_t* b) {
    asm volatile(
        "mma.sync.aligned.m16n8k8.row.col.f32.tf32.tf32.f32 "
        "{%0,%1,%2,%3}, {%4,%5,%6,%7}, {%8,%9}, {%0,%1,%2,%3};"
        : "+f"(c[0]), "+f"(c[1]), "+f"(c[2]), "+f"(c[3])
        : "r"(a[0]), "r"(a[1]), "r"(a[2]), "r"(a[3]), "r"(b[0]), "r"(b[1]));
}
__device__ __forceinline__ void mma_bf16(float* c, const uint32_t* a, uint32_t b0, uint32_t b1) {
    asm volatile(
        "mma.sync.aligned.m16n8k16.row.col.f32.bf16.bf16.f32 "
        "{%0,%1,%2,%3}, {%4,%5,%6,%7}, {%8,%9}, {%0,%1,%2,%3};"
        : "+f"(c[0]), "+f"(c[1]), "+f"(c[2]), "+f"(c[3])
        : "r"(a[0]), "r"(a[1]), "r"(a[2]), "r"(a[3]), "r"(b0), "r"(b1));
}

__global__ void reset_kernel() { g_counter = 0; }

// ---------------------------------------------------------------------------
// wfragB_kernel: Ww [768,128] fp32 -> bf16 fragment layout (m16n8k16 B frags)
// one thread per uint32 (two k-consecutive elements); grid 192 x 256
// ---------------------------------------------------------------------------
__global__ void wfragB_kernel(const float* __restrict__ Ww)
{
    int idx = blockIdx.x * 256 + threadIdx.x;      // 0..49151
    int r    = idx & 3;
    int lane = (idx >> 2) & 31;
    int nt   = (idx >> 7) & 15;
    int kt   = idx >> 11;
    int g = lane >> 2, tig = lane & 3;
    int n = nt * 8 + g;
    int k = kt * 32 + ((r >> 1) << 4) + ((r & 1) << 3) + 2 * tig;
    g_WfragB[idx] = pack_bf2(Ww[k * 128 + n], Ww[(k + 1) * 128 + n]);
}

// ---------------------------------------------------------------------------
// w1frag_kernel: W1 [1152,576] fp32 -> tf32 fragment layout
// ---------------------------------------------------------------------------
__global__ void w1frag_kernel(const float* __restrict__ W1)
{
    int idx = blockIdx.x * 256 + threadIdx.x;      // 0..663551
    int k = idx / 576, c = idx - k * 576;
    int kt = k >> 5, kr = k & 31;
    int ks = kr >> 3, k8 = kr & 7, tig = k8 & 3, slot = k8 >> 2;
    int nt = c >> 3, gid = c & 7;
    int lane = gid * 4 + tig;
    g_W1frag[(((kt * 72 + nt) * 4 + ks) * 32 + lane) * 2 + slot] =
        __uint_as_float(f2tf(W1[idx]));
}

// ---------------------------------------------------------------------------
// side_kernel: persistent; per (b,side): bf16 MMA [node;neigh]@Ww, attention
// grid 296, block 256 (8 warps), dyn smem 61700 B
// ---------------------------------------------------------------------------
__global__ void __launch_bounds__(256, 2) side_kernel(
    const float* __restrict__ node1, const float* __restrict__ node2,
    const float* __restrict__ neigh1, const float* __restrict__ neigh2,
    const float* __restrict__ dist1, const float* __restrict__ dist2,
    const int* __restrict__ len1, const int* __restrict__ len2,
    const float* __restrict__ bw,
    const float* __restrict__ Wa, const float* __restrict__ ba,
    const float* __restrict__ Wdb, const float* __restrict__ bdb)
{
    extern __shared__ float sm[];
    uint32_t* sAb = (uint32_t*)sm;       // 1792 u32 : [mt(7)][ks(2)][lane(32)][reg(4)]
    float* sWng = sm + 1792;             // 12928 (row0 = wn)
    float* sWa  = sWng + 12928;          // 256
    float* sBw  = sWa + 256;             // 128
    float* sDist= sBw + 128;             // 104
    float* sRaw = sDist + 104;           // 104
    float* sAtt = sRaw + 104;            // 104
    float* sC   = sAtt + 104;            // 8
    __shared__ int sIdx;
    // 15424 floats = 61696 B dyn

    const int tid  = threadIdx.x;
    const int warp = tid >> 5, lane = tid & 31;
    const int gid  = lane >> 2, tig = lane & 3;

    sWa[tid] = Wa[tid];
    if (tid < 128) sBw[tid] = bw[tid];

    const float bav = ba[0], wdbv = Wdb[0], bdbv = bdb[0];

    while (true) {
        __syncthreads();
        if (tid == 0) sIdx = (int)atomicAdd(&g_counter, 1u);
        __syncthreads();
        const int item = sIdx;
        if (item >= 2 * BATCH) break;
        const int b = item >> 1, side = item & 1;

        const float* node  = side ? node2  : node1;
        const float* neigh = side ? neigh2 : neigh1;
        const float* dist  = side ? dist2  : dist1;
        int len = side ? len2[b] : len1[b];
        if (len < 1) len = 1; if (len > NMAXN) len = NMAXN;
        const int M = len + 1;
        const int mcount = (M + 15) >> 4;

        if (tid < NMAXN) sDist[tid] = dist[(size_t)b * NMAXN + tid];
#pragma unroll
        for (int i = 0; i < 7; ++i) sAb[tid + i * 256] = 0u;

        const float* nodeRow   = node  + (size_t)b * HD;
        const float* neighBase = neigh + (size_t)b * NMAXN * HD;

        // staging slots: f = tid + i*256 indexes a float4 (row r = f>>3, k-quad j = f&7)
        int nact = 0;
        const float* srcp[4];
        int sbase[4];
#pragma unroll
        for (int i = 0; i < 4; ++i) {
            int f = tid + i * 256;
            if (f < M * 8) {
                int r = f >> 3, j = f & 7;
                int mt = r >> 4, r16 = r & 15, g8 = r16 & 7, hib = r16 >> 3;
                int ks = j >> 2, half = (j >> 1) & 1, tg = (j & 1) * 2;
                srcp[i]  = (r == 0 ? nodeRow : neighBase + (size_t)(r - 1) * HD) + j * 4;
                sbase[i] = ((mt * 2 + ks) * 32 + g8 * 4 + tg) * 4 + half * 2 + hib;
                nact = i + 1;
            }
        }

        float acc[7][2][4];
#pragma unroll
        for (int mt = 0; mt < 7; ++mt)
#pragma unroll
            for (int ni = 0; ni < 2; ++ni)
#pragma unroll
                for (int q = 0; q < 4; ++q) acc[mt][ni][q] = 0.f;

        float4 v[4];
#pragma unroll
        for (int i = 0; i < 4; ++i) if (i < nact) v[i] = *(const float4*)(srcp[i]);

        __syncthreads();

        for (int kt = 0; kt < 24; ++kt) {
            // commit prefetched tile (fp32 -> bf16x2, fragment-ordered)
#pragma unroll
            for (int i = 0; i < 4; ++i) {
                if (i < nact) {
                    sAb[sbase[i]]     = pack_bf2(v[i].x, v[i].y);
                    sAb[sbase[i] + 4] = pack_bf2(v[i].z, v[i].w);
                }
            }
            if (kt < 23) {
#pragma unroll
                for (int i = 0; i < 4; ++i)
                    if (i < nact) v[i] = *(const float4*)(srcp[i] + (kt + 1) * 32);
            }
            __syncthreads();

            // B fragments: one LDG.128 per n-tile
            const uint4 bq0 = *(const uint4*)(g_WfragB + ((kt * 16 + 2 * warp)     * 32 + lane) * 4);
            const uint4 bq1 = *(const uint4*)(g_WfragB + ((kt * 16 + 2 * warp + 1) * 32 + lane) * 4);
#pragma unroll
            for (int ks = 0; ks < 2; ++ks) {
#pragma unroll
                for (int mt = 0; mt < 7; ++mt) {
                    if (mt >= mcount) break;
                    uint4 av = *(const uint4*)(sAb + ((mt * 2 + ks) * 32 + lane) * 4);
                    const uint32_t* a = (const uint32_t*)&av;
                    const uint32_t* p0 = (const uint32_t*)&bq0;
                    const uint32_t* p1 = (const uint32_t*)&bq1;
                    mma_bf16(acc[mt][0], a, p0[2 * ks], p0[2 * ks + 1]);
                    mma_bf16(acc[mt][1], a, p1[2 * ks], p1[2 * ks + 1]);
                }
            }
            __syncthreads();
        }

        // epilogue: + bw, scatter into sWng (D frag layout same as k8)
#pragma unroll
        for (int mt = 0; mt < 7; ++mt) {
            if (mt >= mcount) break;
            int r0 = mt * 16 + gid, r1 = r0 + 8;
#pragma unroll
            for (int ni = 0; ni < 2; ++ni) {
                int cc = (2 * warp + ni) * 8 + tig * 2;
                if (r0 < M) {
                    float2 o = { acc[mt][ni][0] + sBw[cc], acc[mt][ni][1] + sBw[cc + 1] };
                    *(float2*)(sWng + r0 * 128 + cc) = o;
                }
                if (r1 < M) {
                    float2 o = { acc[mt][ni][2] + sBw[cc], acc[mt][ni][3] + sBw[cc + 1] };
                    *(float2*)(sWng + r1 * 128 + cc) = o;
                }
            }
        }
        __syncthreads();

        // attention dots
        for (int r = warp; r < M; r += 8) {
            const float* wrow = sWng + r * 128;
            const float* wa = (r == 0) ? sWa : (sWa + 128);
            float p = 0.f;
#pragma unroll
            for (int q = 0; q < 4; ++q) p += wrow[lane + 32 * q] * wa[lane + 32 * q];
#pragma unroll
            for (int o = 16; o > 0; o >>= 1) p += __shfl_xor_sync(0xffffffffu, p, o);
            if (lane == 0) { if (r == 0) sC[0] = p; else sRaw[r - 1] = p; }
        }
        __syncthreads();

        // warp 0: leaky_relu + dist bias, masked softmax
        if (warp == 0) {
            float c = sC[0];
            float sc[4], ev[4];
            float mx = -3.4e38f;
#pragma unroll
            for (int q = 0; q < 4; ++q) {
                int n = lane + 32 * q;
                float vv = -3.4e38f;
                if (n < len) {
                    float x = c + sRaw[n] + bav;
                    x = (x > 0.f) ? x : 0.01f * x;
                    vv = x + sDist[n] * wdbv + bdbv;
                }
                sc[q] = vv; mx = fmaxf(mx, vv);
            }
#pragma unroll
            for (int o = 16; o > 0; o >>= 1) mx = fmaxf(mx, __shfl_xor_sync(0xffffffffu, mx, o));
            float s = 0.f;
#pragma unroll
            for (int q = 0; q < 4; ++q) {
                int n = lane + 32 * q;
                float e = (n < len) ? expf(sc[q] - mx) : 0.f;
                ev[q] = e; s += e;
            }
#pragma unroll
            for (int o = 16; o > 0; o >>= 1) s += __shfl_xor_sync(0xffffffffu, s, o);
            float inv = 1.f / s;
#pragma unroll
            for (int q = 0; q < 4; ++q) {
                int n = lane + 32 * q;
                if (n < NMAXN) sAtt[n] = ev[q] * inv;
            }
        }
        __syncthreads();

        // ctx & sim
        if (tid < 128) {
            float ctx = 0.f;
            for (int n = 0; n < len; ++n) ctx += sAtt[n] * sWng[(n + 1) * 128 + tid];
            g_sim[(size_t)b * 256 + side * 128 + tid] = ctx * sWng[tid];
        }
    }
}

// ---------------------------------------------------------------------------
// xneigh = relu([sim1,sim2]) @ Wn + bn     grid 256 (4 rows/block), block 256
// ---------------------------------------------------------------------------
__global__ void __launch_bounds__(256) xneigh_kernel(
    const float* __restrict__ Wn, const float* __restrict__ bn)
{
    __shared__ float sS[4 * 256];
    const int b0 = blockIdx.x * 4;
    const int tid = threadIdx.x;
#pragma unroll
    for (int r = 0; r < 4; ++r)
        sS[r * 256 + tid] = fmaxf(g_sim[(size_t)(b0 + r) * 256 + tid], 0.f);
    __syncthreads();
    float acc[4];
    const float bnv = bn[tid];
#pragma unroll
    for (int r = 0; r < 4; ++r) acc[r] = bnv;
    for (int k0 = 0; k0 < 256; k0 += 4) {
        float w0 = Wn[(k0 + 0) * 256 + tid];
        float w1 = Wn[(k0 + 1) * 256 + tid];
        float w2 = Wn[(k0 + 2) * 256 + tid];
        float w3 = Wn[(k0 + 3) * 256 + tid];
#pragma unroll
        for (int r = 0; r < 4; ++r) {
            acc[r] += sS[r * 256 + k0] * w0;
            acc[r] += sS[r * 256 + k0 + 1] * w1;
            acc[r] += sS[r * 256 + k0 + 2] * w2;
            acc[r] += sS[r * 256 + k0 + 3] * w3;
        }
    }
#pragma unroll
    for (int r = 0; r < 4; ++r) g_xn[(size_t)(b0 + r) * 256 + tid] = acc[r];
}

// ---------------------------------------------------------------------------
// build_h: g_h[b][0:768]=pooled, [768:896]=coord, [896:1152]=xneigh
// ---------------------------------------------------------------------------
__global__ void build_h_kernel(
    const float* __restrict__ pooled, const float* __restrict__ x_coord,
    const float* __restrict__ Wc, const float* __restrict__ bc)
{
    int idx = blockIdx.x * 256 + threadIdx.x;
    int b = idx / 1152, j = idx - b * 1152;
    float v;
    if (j < 768)       v = pooled[(size_t)b * 768 + j];
    else if (j < 896)  v = x_coord[b] * Wc[j - 768] + bc[j - 768];
    else               v = g_xn[(size_t)b * 256 + (j - 896)];
    g_h[idx] = v;
}

// ---------------------------------------------------------------------------
// head_mm: g_h1 = gelu(g_h @ W1 + b1)   tf32, grid (32,9) = 32x64 tiles
// ---------------------------------------------------------------------------
__global__ void __launch_bounds__(256) head_mm_kernel(const float* __restrict__ b1)
{
    __shared__ float sA[1024];     // [mt(2)][ks(4)][lane(32)][4]

    const int tid  = threadIdx.x;
    const int warp = tid >> 5, lane = tid & 31;
    const int gid  = lane >> 2, tig = lane & 3;
    const int m0   = blockIdx.x * 32;
    const int ntg  = blockIdx.y * 8 + warp;

    // one staging slot per thread: f = tid (32 rows x 8 float4)
    const float* srcp;
    int sbase;
    {
        int f = tid;
        int r = f >> 3;
        int mt = r >> 4, r16 = r & 15, g8 = r16 & 7, hi = r16 >> 3;
        int ksl = (f & 7) >> 1, kh = f & 1;
        srcp  = g_h + (size_t)(m0 + r) * 1152 + (f & 7) * 4;
        sbase = (mt * 4 + ksl) * 128 + (g8 * 4) * 4 + (kh * 2 + hi);
    }

    float acc[2][4];
#pragma unroll
    for (int mt = 0; mt < 2; ++mt)
#pragma unroll
        for (int q = 0; q < 4; ++q) acc[mt][q] = 0.f;

    float4 v = *(const float4*)(srcp);

    for (int kt = 0; kt < 36; ++kt) {
        sA[sbase + 0 ] = __uint_as_float(f2tf(v.x));
        sA[sbase + 4 ] = __uint_as_float(f2tf(v.y));
        sA[sbase + 8 ] = __uint_as_float(f2tf(v.z));
        sA[sbase + 12] = __uint_as_float(f2tf(v.w));
        if (kt < 35) v = *(const float4*)(srcp + (kt + 1) * 32);
        __syncthreads();

        uint32_t bfr[4][2];
#pragma unroll
        for (int ks = 0; ks < 4; ++ks) {
            float2 bv = *(const float2*)(g_W1frag +
                (((kt * 72 + ntg) * 4 + ks) * 32 + lane) * 2);
            bfr[ks][0] = __float_as_uint(bv.x);
            bfr[ks][1] = __float_as_uint(bv.y);
        }
#pragma unroll
        for (int ks = 0; ks < 4; ++ks) {
#pragma unroll
            for (int mt = 0; mt < 2; ++mt) {
                float4 av = *(const float4*)(sA + (mt * 4 + ks) * 128 + lane * 4);
                uint32_t a[4] = { __float_as_uint(av.x), __float_as_uint(av.y),
                                  __float_as_uint(av.z), __float_as_uint(av.w) };
                mma_tf32(acc[mt], a, bfr[ks]);
            }
        }
        __syncthreads();
    }

    const int cc = ntg * 8 + tig * 2;
    const float bv0 = b1[cc], bv1 = b1[cc + 1];
#pragma unroll
    for (int mt = 0; mt < 2; ++mt) {
        int r0 = m0 + mt * 16 + gid, r1 = r0 + 8;
        float x;
        x = acc[mt][0] + bv0; g_h1[(size_t)r0 * 576 + cc]     = x * normcdff(x);
        x = acc[mt][1] + bv1; g_h1[(size_t)r0 * 576 + cc + 1] = x * normcdff(x);
        x = acc[mt][2] + bv0; g_h1[(size_t)r1 * 576 + cc]     = x * normcdff(x);
        x = acc[mt][3] + bv1; g_h1[(size_t)r1 * 576 + cc + 1] = x * normcdff(x);
    }
}

// ---------------------------------------------------------------------------
// logits: out = log_softmax(g_h1 @ W2 + b2)   grid 128, block 256
// ---------------------------------------------------------------------------
__global__ void logits_kernel(const float* __restrict__ W2, const float* __restrict__ b2,
                              float* __restrict__ out)
{
    __shared__ float sW2[1152];
    const int tid = threadIdx.x;
    const int lane = tid & 31, warp = tid >> 5;
    for (int j = tid; j < 1152; j += 256) sW2[j] = W2[j];
    __syncthreads();

    const int r = blockIdx.x * 8 + warp;
    float p0 = 0.f, p1 = 0.f;
    const float* hrow = g_h1 + (size_t)r * 576;
#pragma unroll
    for (int q = 0; q < 18; ++q) {
        int j = lane + 32 * q;
        float h = hrow[j];
        p0 += h * sW2[2 * j];
        p1 += h * sW2[2 * j + 1];
    }
#pragma unroll
    for (int o = 16; o > 0; o >>= 1) {
        p0 += __shfl_xor_sync(0xffffffffu, p0, o);
        p1 += __shfl_xor_sync(0xffffffffu, p1, o);
    }
    if (lane == 0) {
        float l0 = p0 + b2[0], l1 = p1 + b2[1];
        float m = fmaxf(l0, l1);
        float lse = m + logf(expf(l0 - m) + expf(l1 - m));
        out[(size_t)r * 2 + 0] = l0 - lse;
        out[(size_t)r * 2 + 1] = l1 - lse;
    }
}

// ---------------------------------------------------------------------------
extern "C" void kernel_launch(void* const* d_in, const int* in_sizes, int n_in,
                              void* d_out, int out_size)
{
    const float* pooled = (const float*)d_in[0];
    const float* x_coord= (const float*)d_in[1];
    const float* node1  = (const float*)d_in[2];
    const float* node2  = (const float*)d_in[3];
    const float* neigh1 = (const float*)d_in[4];
    const float* neigh2 = (const float*)d_in[5];
    const float* dist1  = (const float*)d_in[6];
    const float* dist2  = (const float*)d_in[7];
    const int*   len1   = (const int*)d_in[8];
    const int*   len2   = (const int*)d_in[9];
    const float* Ww  = (const float*)d_in[10];
    const float* bw  = (const float*)d_in[11];
    const float* Wa  = (const float*)d_in[12];
    const float* ba  = (const float*)d_in[13];
    const float* Wdb = (const float*)d_in[14];
    const float* bdb = (const float*)d_in[15];
    const float* Wn  = (const float*)d_in[16];
    const float* bn  = (const float*)d_in[17];
    const float* Wc  = (const float*)d_in[18];
    const float* bc  = (const float*)d_in[19];
    const float* W1  = (const float*)d_in[20];
    const float* b1  = (const float*)d_in[21];
    const float* W2  = (const float*)d_in[22];
    const float* b2  = (const float*)d_in[23];
    float* out = (float*)d_out;

    reset_kernel<<<1, 1>>>();
    wfragB_kernel<<<192, 256>>>(Ww);
    w1frag_kernel<<<2592, 256>>>(W1);

    const int smB = 15424 * (int)sizeof(float);   // 61696 B
    cudaFuncSetAttribute(side_kernel, cudaFuncAttributeMaxDynamicSharedMemorySize, smB);
    side_kernel<<<296, 256, smB>>>(node1, node2, neigh1, neigh2,
                                   dist1, dist2, len1, len2,
                                   bw, Wa, ba, Wdb, bdb);

    xneigh_kernel<<<BATCH / 4, 256>>>(Wn, bn);

    build_h_kernel<<<(BATCH * 1152) / 256, 256>>>(pooled, x_coord, Wc, bc);

    head_mm_kernel<<<dim3(32, 9), 256>>>(b1);

    logits_kernel<<<BATCH / 8, 256>>>(W2, b2, out);
}

// round 5
// speedup vs baseline: 7.2006x; 1.1155x over previous
#include <cuda_runtime.h>
#include <cuda_bf16.h>
#include <math.h>
#include <stdint.h>

#define BATCH 1024
#define NMAXN 100
#define HD    768

// ---------------- scratch (no allocations allowed) ----------------
__device__ float g_sim[BATCH * 256];
__device__ float g_xn [BATCH * 256];
__device__ float g_h  [BATCH * 1152];
__device__ float g_h1 [BATCH * 576];
__device__ unsigned g_counter;
// Ww in bf16 fragment layout for m16n8k16: [kt(24)][nt(16)][lane(32)][reg(4)] (uint32 = bf16x2)
__device__ __align__(16) uint32_t g_WfragB[24 * 16 * 32 * 4];
// W1 in tf32 fragment layout: [kt(36)][nt(72)][ks(4)][lane(32)][slot(2)]
__device__ float g_W1frag[36 * 72 * 4 * 32 * 2];

__device__ __forceinline__ uint32_t f2tf(float x) {
    uint32_t t; asm("cvt.rna.tf32.f32 %0, %1;" : "=r"(t) : "f"(x)); return t;
}
__device__ __forceinline__ uint32_t pack_bf2(float lo, float hi) {
    __nv_bfloat162 p = __float22bfloat162_rn(make_float2(lo, hi));
    return *(uint32_t*)&p;
}

__device__ __forceinline__ void mma_tf32(float* c, const uint32_t* a, const uint32_t* b) {
    asm volatile(
        "mma.sync.aligned.m16n8k8.row.col.f32.tf32.tf32.f32 "
        "{%0,%1,%2,%3}, {%4,%5,%6,%7}, {%8,%9}, {%0,%1,%2,%3};"
        : "+f"(c[0]), "+f"(c[1]), "+f"(c[2]), "+f"(c[3])
        : "r"(a[0]), "r"(a[1]), "r"(a[2]), "r"(a[3]), "r"(b[0]), "r"(b[1]));
}
__device__ __forceinline__ void mma_bf16(float* c, const uint32_t* a, uint32_t b0, uint32_t b1) {
    asm volatile(
        "mma.sync.aligned.m16n8k16.row.col.f32.bf16.bf16.f32 "
        "{%0,%1,%2,%3}, {%4,%5,%6,%7}, {%8,%9}, {%0,%1,%2,%3};"
        : "+f"(c[0]), "+f"(c[1]), "+f"(c[2]), "+f"(c[3])
        : "r"(a[0]), "r"(a[1]), "r"(a[2]), "r"(a[3]), "r"(b0), "r"(b1));
}

// ---------------------------------------------------------------------------
// prep_kernel: counter reset + Ww bf16 frags + W1 tf32 frags in ONE launch
// grid 2784 x 256
// ---------------------------------------------------------------------------
__global__ void prep_kernel(const float* __restrict__ Ww, const float* __restrict__ W1)
{
    if (blockIdx.x == 0 && threadIdx.x == 0) g_counter = 0u;
    if (blockIdx.x < 192) {
        int idx = blockIdx.x * 256 + threadIdx.x;      // 0..49151
        int r    = idx & 3;
        int lane = (idx >> 2) & 31;
        int nt   = (idx >> 7) & 15;
        int kt   = idx >> 11;
        int g = lane >> 2, tig = lane & 3;
        int n = nt * 8 + g;
        int k = kt * 32 + ((r >> 1) << 4) + ((r & 1) << 3) + 2 * tig;
        g_WfragB[idx] = pack_bf2(Ww[k * 128 + n], Ww[(k + 1) * 128 + n]);
    } else {
        int idx = (blockIdx.x - 192) * 256 + threadIdx.x;   // 0..663551
        int k = idx / 576, c = idx - k * 576;
        int kt = k >> 5, kr = k & 31;
        int ks = kr >> 3, k8 = kr & 7, tig = k8 & 3, slot = k8 >> 2;
        int nt = c >> 3, gid = c & 7;
        int lane = gid * 4 + tig;
        g_W1frag[(((kt * 72 + nt) * 4 + ks) * 32 + lane) * 2 + slot] =
            __uint_as_float(f2tf(W1[idx]));
    }
}

// ---------------------------------------------------------------------------
// side_kernel: persistent; per (b,side): bf16 MMA [node;neigh]@Ww, attention
// grid 296, block 256 (8 warps), dyn smem 70880 B
// double-buffered A staging (1 barrier per k-tile), B frags prefetched 1 ahead
// ---------------------------------------------------------------------------
__global__ void __launch_bounds__(256, 2) side_kernel(
    const float* __restrict__ node1, const float* __restrict__ node2,
    const float* __restrict__ neigh1, const float* __restrict__ neigh2,
    const float* __restrict__ dist1, const float* __restrict__ dist2,
    const int* __restrict__ len1, const int* __restrict__ len2,
    const float* __restrict__ bw,
    const float* __restrict__ Wa, const float* __restrict__ ba,
    const float* __restrict__ Wdb, const float* __restrict__ bdb)
{
    extern __shared__ float sm[];
    uint32_t* sAb = (uint32_t*)sm;       // 2 x 1792 u32 : [buf][mt(7)][ks(2)][lane(32)][reg(4)]
    float* sWng = sm + 3584;             // 101 rows x stride 132 = 13332 (row0 = wn)
    float* sWa  = sWng + 13332;          // 256
    float* sBw  = sWa + 256;             // 128
    float* sDist= sBw + 128;             // 104
    float* sRaw = sDist + 104;           // 104
    float* sAtt = sRaw + 104;            // 104
    float* sC   = sAtt + 104;            // 8
    __shared__ int sIdx;
    // 17720 floats = 70880 B dyn

    const int tid  = threadIdx.x;
    const int warp = tid >> 5, lane = tid & 31;
    const int gid  = lane >> 2, tig = lane & 3;

    sWa[tid] = Wa[tid];
    if (tid < 128) sBw[tid] = bw[tid];

    const float bav = ba[0], wdbv = Wdb[0], bdbv = bdb[0];

    while (true) {
        __syncthreads();
        if (tid == 0) sIdx = (int)atomicAdd(&g_counter, 1u);
        __syncthreads();
        const int item = sIdx;
        if (item >= 2 * BATCH) break;
        const int b = item >> 1, side = item & 1;

        const float* node  = side ? node2  : node1;
        const float* neigh = side ? neigh2 : neigh1;
        const float* dist  = side ? dist2  : dist1;
        int len = side ? len2[b] : len1[b];
        if (len < 1) len = 1; if (len > NMAXN) len = NMAXN;
        const int M = len + 1;
        const int mcount = (M + 15) >> 4;

        if (tid < NMAXN) sDist[tid] = dist[(size_t)b * NMAXN + tid];

        const float* nodeRow   = node  + (size_t)b * HD;
        const float* neighBase = neigh + (size_t)b * NMAXN * HD;

        // staging slots: f = tid + i*256 indexes a float4 (row r = f>>3, k-quad j = f&7)
        int nact = 0;
        const float* srcp[4];
        int sbase[4];
#pragma unroll
        for (int i = 0; i < 4; ++i) {
            int f = tid + i * 256;
            if (f < M * 8) {
                int r = f >> 3, j = f & 7;
                int mt = r >> 4, r16 = r & 15, g8 = r16 & 7, hib = r16 >> 3;
                int ks = j >> 2, half = (j >> 1) & 1, tg = (j & 1) * 2;
                srcp[i]  = (r == 0 ? nodeRow : neighBase + (size_t)(r - 1) * HD) + j * 4;
                sbase[i] = ((mt * 2 + ks) * 32 + g8 * 4 + tg) * 4 + half * 2 + hib;
                nact = i + 1;
            }
        }

        float acc[7][2][4];
#pragma unroll
        for (int mt = 0; mt < 7; ++mt)
#pragma unroll
            for (int ni = 0; ni < 2; ++ni)
#pragma unroll
                for (int q = 0; q < 4; ++q) acc[mt][ni][q] = 0.f;

        // ---- prologue: stage kt=0 into buf0, prefetch kt=1 + B(kt=0) ----
        float4 v[4];
#pragma unroll
        for (int i = 0; i < 4; ++i) if (i < nact) v[i] = *(const float4*)(srcp[i]);

        uint4 bq0 = *(const uint4*)(g_WfragB + ((2 * warp)     * 32 + lane) * 4);
        uint4 bq1 = *(const uint4*)(g_WfragB + ((2 * warp + 1) * 32 + lane) * 4);

#pragma unroll
        for (int i = 0; i < 4; ++i) {
            if (i < nact) {
                sAb[sbase[i]]     = pack_bf2(v[i].x, v[i].y);
                sAb[sbase[i] + 4] = pack_bf2(v[i].z, v[i].w);
            }
        }
#pragma unroll
        for (int i = 0; i < 4; ++i)
            if (i < nact) v[i] = *(const float4*)(srcp[i] + 32);
        __syncthreads();

        // ---- mainloop: 1 barrier per k-tile ----
        for (int kt = 0; kt < 24; ++kt) {
            const uint32_t* cur = sAb + (kt & 1) * 1792;
            uint32_t* nxt = sAb + ((kt + 1) & 1) * 1792;

            uint4 nb0, nb1;
            if (kt < 23) {
                // prefetch B for kt+1
                nb0 = *(const uint4*)(g_WfragB + (((kt + 1) * 16 + 2 * warp)     * 32 + lane) * 4);
                nb1 = *(const uint4*)(g_WfragB + (((kt + 1) * 16 + 2 * warp + 1) * 32 + lane) * 4);
                // commit kt+1 A tile (loaded a full iteration ago) into the other buffer
#pragma unroll
                for (int i = 0; i < 4; ++i) {
                    if (i < nact) {
                        nxt[sbase[i]]     = pack_bf2(v[i].x, v[i].y);
                        nxt[sbase[i] + 4] = pack_bf2(v[i].z, v[i].w);
                    }
                }
                if (kt < 22) {
#pragma unroll
                    for (int i = 0; i < 4; ++i)
                        if (i < nact) v[i] = *(const float4*)(srcp[i] + (kt + 2) * 32);
                }
            }

            const uint32_t* p0 = (const uint32_t*)&bq0;
            const uint32_t* p1 = (const uint32_t*)&bq1;
#pragma unroll
            for (int ks = 0; ks < 2; ++ks) {
#pragma unroll
                for (int mt = 0; mt < 7; ++mt) {
                    if (mt >= mcount) break;
                    uint4 av = *(const uint4*)(cur + ((mt * 2 + ks) * 32 + lane) * 4);
                    const uint32_t* a = (const uint32_t*)&av;
                    mma_bf16(acc[mt][0], a, p0[2 * ks], p0[2 * ks + 1]);
                    mma_bf16(acc[mt][1], a, p1[2 * ks], p1[2 * ks + 1]);
                }
            }
            if (kt < 23) { bq0 = nb0; bq1 = nb1; }
            __syncthreads();
        }

        // epilogue: + bw, scatter into sWng (stride 132, conflict-free-ish)
#pragma unroll
        for (int mt = 0; mt < 7; ++mt) {
            if (mt >= mcount) break;
            int r0 = mt * 16 + gid, r1 = r0 + 8;
#pragma unroll
            for (int ni = 0; ni < 2; ++ni) {
                int cc = (2 * warp + ni) * 8 + tig * 2;
                if (r0 < M) {
                    float2 o = { acc[mt][ni][0] + sBw[cc], acc[mt][ni][1] + sBw[cc + 1] };
                    *(float2*)(sWng + r0 * 132 + cc) = o;
                }
                if (r1 < M) {
                    float2 o = { acc[mt][ni][2] + sBw[cc], acc[mt][ni][3] + sBw[cc + 1] };
                    *(float2*)(sWng + r1 * 132 + cc) = o;
                }
            }
        }
        __syncthreads();

        // attention dots
        for (int r = warp; r < M; r += 8) {
            const float* wrow = sWng + r * 132;
            const float* wa = (r == 0) ? sWa : (sWa + 128);
            float p = 0.f;
#pragma unroll
            for (int q = 0; q < 4; ++q) p += wrow[lane + 32 * q] * wa[lane + 32 * q];
#pragma unroll
            for (int o = 16; o > 0; o >>= 1) p += __shfl_xor_sync(0xffffffffu, p, o);
            if (lane == 0) { if (r == 0) sC[0] = p; else sRaw[r - 1] = p; }
        }
        __syncthreads();

        // warp 0: leaky_relu + dist bias, masked softmax
        if (warp == 0) {
            float c = sC[0];
            float sc[4], ev[4];
            float mx = -3.4e38f;
#pragma unroll
            for (int q = 0; q < 4; ++q) {
                int n = lane + 32 * q;
                float vv = -3.4e38f;
                if (n < len) {
                    float x = c + sRaw[n] + bav;
                    x = (x > 0.f) ? x : 0.01f * x;
                    vv = x + sDist[n] * wdbv + bdbv;
                }
                sc[q] = vv; mx = fmaxf(mx, vv);
            }
#pragma unroll
            for (int o = 16; o > 0; o >>= 1) mx = fmaxf(mx, __shfl_xor_sync(0xffffffffu, mx, o));
            float s = 0.f;
#pragma unroll
            for (int q = 0; q < 4; ++q) {
                int n = lane + 32 * q;
                float e = (n < len) ? expf(sc[q] - mx) : 0.f;
                ev[q] = e; s += e;
            }
#pragma unroll
            for (int o = 16; o > 0; o >>= 1) s += __shfl_xor_sync(0xffffffffu, s, o);
            float inv = 1.f / s;
#pragma unroll
            for (int q = 0; q < 4; ++q) {
                int n = lane + 32 * q;
                if (n < NMAXN) sAtt[n] = ev[q] * inv;
            }
        }
        __syncthreads();

        // ctx & sim
        if (tid < 128) {
            float ctx = 0.f;
            for (int n = 0; n < len; ++n) ctx += sAtt[n] * sWng[(n + 1) * 132 + tid];
            g_sim[(size_t)b * 256 + side * 128 + tid] = ctx * sWng[tid];
        }
    }
}

// ---------------------------------------------------------------------------
// xneigh = relu([sim1,sim2]) @ Wn + bn     grid 256 (4 rows/block), block 256
// ---------------------------------------------------------------------------
__global__ void __launch_bounds__(256) xneigh_kernel(
    const float* __restrict__ Wn, const float* __restrict__ bn)
{
    __shared__ float sS[4 * 256];
    const int b0 = blockIdx.x * 4;
    const int tid = threadIdx.x;
#pragma unroll
    for (int r = 0; r < 4; ++r)
        sS[r * 256 + tid] = fmaxf(g_sim[(size_t)(b0 + r) * 256 + tid], 0.f);
    __syncthreads();
    float acc[4];
    const float bnv = bn[tid];
#pragma unroll
    for (int r = 0; r < 4; ++r) acc[r] = bnv;
    for (int k0 = 0; k0 < 256; k0 += 4) {
        float w0 = Wn[(k0 + 0) * 256 + tid];
        float w1 = Wn[(k0 + 1) * 256 + tid];
        float w2 = Wn[(k0 + 2) * 256 + tid];
        float w3 = Wn[(k0 + 3) * 256 + tid];
#pragma unroll
        for (int r = 0; r < 4; ++r) {
            acc[r] += sS[r * 256 + k0] * w0;
            acc[r] += sS[r * 256 + k0 + 1] * w1;
            acc[r] += sS[r * 256 + k0 + 2] * w2;
            acc[r] += sS[r * 256 + k0 + 3] * w3;
        }
    }
#pragma unroll
    for (int r = 0; r < 4; ++r) g_xn[(size_t)(b0 + r) * 256 + tid] = acc[r];
}

// ---------------------------------------------------------------------------
// build_h: g_h[b][0:768]=pooled, [768:896]=coord, [896:1152]=xneigh
// ---------------------------------------------------------------------------
__global__ void build_h_kernel(
    const float* __restrict__ pooled, const float* __restrict__ x_coord,
    const float* __restrict__ Wc, const float* __restrict__ bc)
{
    int idx = blockIdx.x * 256 + threadIdx.x;
    int b = idx / 1152, j = idx - b * 1152;
    float v;
    if (j < 768)       v = pooled[(size_t)b * 768 + j];
    else if (j < 896)  v = x_coord[b] * Wc[j - 768] + bc[j - 768];
    else               v = g_xn[(size_t)b * 256 + (j - 896)];
    g_h[idx] = v;
}

// ---------------------------------------------------------------------------
// head_mm: g_h1 = gelu(g_h @ W1 + b1)   tf32, grid (32,9) = 32x64 tiles
// ---------------------------------------------------------------------------
__global__ void __launch_bounds__(256) head_mm_kernel(const float* __restrict__ b1)
{
    __shared__ float sA[1024];     // [mt(2)][ks(4)][lane(32)][4]

    const int tid  = threadIdx.x;
    const int warp = tid >> 5, lane = tid & 31;
    const int gid  = lane >> 2, tig = lane & 3;
    const int m0   = blockIdx.x * 32;
    const int ntg  = blockIdx.y * 8 + warp;

    const float* srcp;
    int sbase;
    {
        int f = tid;
        int r = f >> 3;
        int mt = r >> 4, r16 = r & 15, g8 = r16 & 7, hi = r16 >> 3;
        int ksl = (f & 7) >> 1, kh = f & 1;
        srcp  = g_h + (size_t)(m0 + r) * 1152 + (f & 7) * 4;
        sbase = (mt * 4 + ksl) * 128 + (g8 * 4) * 4 + (kh * 2 + hi);
    }

    float acc[2][4];
#pragma unroll
    for (int mt = 0; mt < 2; ++mt)
#pragma unroll
        for (int q = 0; q < 4; ++q) acc[mt][q] = 0.f;

    float4 v = *(const float4*)(srcp);

    for (int kt = 0; kt < 36; ++kt) {
        sA[sbase + 0 ] = __uint_as_float(f2tf(v.x));
        sA[sbase + 4 ] = __uint_as_float(f2tf(v.y));
        sA[sbase + 8 ] = __uint_as_float(f2tf(v.z));
        sA[sbase + 12] = __uint_as_float(f2tf(v.w));
        if (kt < 35) v = *(const float4*)(srcp + (kt + 1) * 32);
        __syncthreads();

        uint32_t bfr[4][2];
#pragma unroll
        for (int ks = 0; ks < 4; ++ks) {
            float2 bv = *(const float2*)(g_W1frag +
                (((kt * 72 + ntg) * 4 + ks) * 32 + lane) * 2);
            bfr[ks][0] = __float_as_uint(bv.x);
            bfr[ks][1] = __float_as_uint(bv.y);
        }
#pragma unroll
        for (int ks = 0; ks < 4; ++ks) {
#pragma unroll
            for (int mt = 0; mt < 2; ++mt) {
                float4 av = *(const float4*)(sA + (mt * 4 + ks) * 128 + lane * 4);
                uint32_t a[4] = { __float_as_uint(av.x), __float_as_uint(av.y),
                                  __float_as_uint(av.z), __float_as_uint(av.w) };
                mma_tf32(acc[mt], a, bfr[ks]);
            }
        }
        __syncthreads();
    }

    const int cc = ntg * 8 + tig * 2;
    const float bv0 = b1[cc], bv1 = b1[cc + 1];
#pragma unroll
    for (int mt = 0; mt < 2; ++mt) {
        int r0 = m0 + mt * 16 + gid, r1 = r0 + 8;
        float x;
        x = acc[mt][0] + bv0; g_h1[(size_t)r0 * 576 + cc]     = x * normcdff(x);
        x = acc[mt][1] + bv1; g_h1[(size_t)r0 * 576 + cc + 1] = x * normcdff(x);
        x = acc[mt][2] + bv0; g_h1[(size_t)r1 * 576 + cc]     = x * normcdff(x);
        x = acc[mt][3] + bv1; g_h1[(size_t)r1 * 576 + cc + 1] = x * normcdff(x);
    }
}

// ---------------------------------------------------------------------------
// logits: out = log_softmax(g_h1 @ W2 + b2)   grid 128, block 256
// ---------------------------------------------------------------------------
__global__ void logits_kernel(const float* __restrict__ W2, const float* __restrict__ b2,
                              float* __restrict__ out)
{
    __shared__ float sW2[1152];
    const int tid = threadIdx.x;
    const int lane = tid & 31, warp = tid >> 5;
    for (int j = tid; j < 1152; j += 256) sW2[j] = W2[j];
    __syncthreads();

    const int r = blockIdx.x * 8 + warp;
    float p0 = 0.f, p1 = 0.f;
    const float* hrow = g_h1 + (size_t)r * 576;
#pragma unroll
    for (int q = 0; q < 18; ++q) {
        int j = lane + 32 * q;
        float h = hrow[j];
        p0 += h * sW2[2 * j];
        p1 += h * sW2[2 * j + 1];
    }
#pragma unroll
    for (int o = 16; o > 0; o >>= 1) {
        p0 += __shfl_xor_sync(0xffffffffu, p0, o);
        p1 += __shfl_xor_sync(0xffffffffu, p1, o);
    }
    if (lane == 0) {
        float l0 = p0 + b2[0], l1 = p1 + b2[1];
        float m = fmaxf(l0, l1);
        float lse = m + logf(expf(l0 - m) + expf(l1 - m));
        out[(size_t)r * 2 + 0] = l0 - lse;
        out[(size_t)r * 2 + 1] = l1 - lse;
    }
}

// ---------------------------------------------------------------------------
extern "C" void kernel_launch(void* const* d_in, const int* in_sizes, int n_in,
                              void* d_out, int out_size)
{
    const float* pooled = (const float*)d_in[0];
    const float* x_coord= (const float*)d_in[1];
    const float* node1  = (const float*)d_in[2];
    const float* node2  = (const float*)d_in[3];
    const float* neigh1 = (const float*)d_in[4];
    const float* neigh2 = (const float*)d_in[5];
    const float* dist1  = (const float*)d_in[6];
    const float* dist2  = (const float*)d_in[7];
    const int*   len1   = (const int*)d_in[8];
    const int*   len2   = (const int*)d_in[9];
    const float* Ww  = (const float*)d_in[10];
    const float* bw  = (const float*)d_in[11];
    const float* Wa  = (const float*)d_in[12];
    const float* ba  = (const float*)d_in[13];
    const float* Wdb = (const float*)d_in[14];
    const float* bdb = (const float*)d_in[15];
    const float* Wn  = (const float*)d_in[16];
    const float* bn  = (const float*)d_in[17];
    const float* Wc  = (const float*)d_in[18];
    const float* bc  = (const float*)d_in[19];
    const float* W1  = (const float*)d_in[20];
    const float* b1  = (const float*)d_in[21];
    const float* W2  = (const float*)d_in[22];
    const float* b2  = (const float*)d_in[23];
    float* out = (float*)d_out;

    prep_kernel<<<2784, 256>>>(Ww, W1);

    const int smB = 17720 * (int)sizeof(float);   // 70880 B
    cudaFuncSetAttribute(side_kernel, cudaFuncAttributeMaxDynamicSharedMemorySize, smB);
    side_kernel<<<296, 256, smB>>>(node1, node2, neigh1, neigh2,
                                   dist1, dist2, len1, len2,
                                   bw, Wa, ba, Wdb, bdb);

    xneigh_kernel<<<BATCH / 4, 256>>>(Wn, bn);

    build_h_kernel<<<(BATCH * 1152) / 256, 256>>>(pooled, x_coord, Wc, bc);

    head_mm_kernel<<<dim3(32, 9), 256>>>(b1);

    logits_kernel<<<BATCH / 8, 256>>>(W2, b2, out);
}